// round 13
// baseline (speedup 1.0000x reference)
#include <cuda_runtime.h>
#include <cuda_bf16.h>

#define HLR 128
#define WLR 128
#define HH 512
#define WH 512
#define NPIX (HH*WH)      // 262144
#define NPIX2 (514*512)   // padded mid plane rows 0..513
#define NQ 262144
#define PPL 17424         // padded LR plane: 132*132, data at (y+2, x+2)

typedef unsigned long long ull;

// ---- packed f32x2 helpers (sm_103a: fma.rn.f32x2 -> FFMA2) ----
__device__ __forceinline__ ull pk2(float lo, float hi) {
    ull r; asm("mov.b64 %0, {%1, %2};" : "=l"(r) : "f"(lo), "f"(hi)); return r;
}
__device__ __forceinline__ void upk2(ull v, float& lo, float& hi) {
    asm("mov.b64 {%0, %1}, %2;" : "=f"(lo), "=f"(hi) : "l"(v));
}
__device__ __forceinline__ ull fma2(ull a, ull b, ull c) {
    ull d; asm("fma.rn.f32x2 %0, %1, %2, %3;" : "=l"(d) : "l"(a), "l"(b), "l"(c)); return d;
}
__device__ __forceinline__ ull mul2(ull a, ull b) {
    ull d; asm("mul.rn.f32x2 %0, %1, %2;" : "=l"(d) : "l"(a), "l"(b)); return d;
}

// ---- scratch (device globals: allocation-free) ----
__device__ __align__(16) ulonglong2 g_feat4[16*PPL];   // 4.5 MB padded c4-planes
// mid packed: 2 planes of ulonglong2 = (k0k1,k2k3) and (k4k5,k6k7), permuted+padded
__device__ __align__(16) ulonglong2 g_mid4[2*NPIX2];   // 8.4 MB
__device__ __align__(16) float4 g_G4[9*PPL];           // 2.5 MB padded tap-planes
__device__ __align__(16) ull g_T2[3*9*16*4];           // T k-pairs [o][tap][ph][k2]
__device__ __align__(16) float4 g_pred4[NPIX];         // 4 MB, phase-permuted
__device__ float g_off[16*2];
__device__ float g_r[16*4];
__device__ __align__(16) float g_B[16*512];            // [ph][k*64+c]

// ============ Kernel 1: encoder conv3x3 (blocks 0..511, f32x2) + phase MLP (block 512) ============
__global__ void __launch_bounds__(256)
k_enc_phase(const float* __restrict__ inp,
            const float* __restrict__ ew, const float* __restrict__ eb,
            const float* __restrict__ w1, const float* __restrict__ b1,
            const float* __restrict__ w2, const float* __restrict__ b2,
            const float* __restrict__ rw, const float* __restrict__ rb,
            const float* __restrict__ ow, const float* __restrict__ ob) {
    __shared__ ull sww[27*32];     // enc weights packed [j][c2]
    __shared__ float sb[64];
    __shared__ float sw2[64*65];
    __shared__ float se1[1024];
    __shared__ float se2[1024];
    int t = threadIdx.x;

    if (blockIdx.x < 512) {
        for (int idx = t; idx < 27*32; idx += 256) {
            int j = idx >> 5, c2 = idx & 31;
            sww[idx] = pk2(__ldg(&ew[(2*c2)*27 + j]), __ldg(&ew[(2*c2+1)*27 + j]));
        }
        if (t < 64) sb[t] = __ldg(&eb[t]);
        __syncthreads();

        int px = blockIdx.x*32 + (t & 31);
        int grp = t >> 5;                    // c4 pair {2g, 2g+1}; c2 in {4g..4g+3}
        int x = px & 127, y = px >> 7;

        float in[27];
        #pragma unroll
        for (int ci = 0; ci < 3; ci++)
            #pragma unroll
            for (int ky = 0; ky < 3; ky++) {
                int yy = y + ky - 1;
                bool ry = ((unsigned)yy < 128u);
                #pragma unroll
                for (int kx = 0; kx < 3; kx++) {
                    int xx = x + kx - 1;
                    in[ci*9 + ky*3 + kx] = (ry && ((unsigned)xx < 128u))
                        ? __ldg(&inp[(ci*128 + yy)*128 + xx]) : 0.0f;
                }
            }
        ull a4[4];
        #pragma unroll
        for (int u = 0; u < 4; u++) {
            int c2 = grp*4 + u;
            a4[u] = pk2(sb[2*c2], sb[2*c2+1]);
        }
        #pragma unroll
        for (int j = 0; j < 27; j++) {
            ull fin = pk2(in[j], in[j]);
            #pragma unroll
            for (int u = 0; u < 4; u++)
                a4[u] = fma2(fin, sww[j*32 + grp*4 + u], a4[u]);
        }
        int fidx = (y+2)*132 + (x+2);
        ulonglong2 q0; q0.x = a4[0]; q0.y = a4[1];
        ulonglong2 q1; q1.x = a4[2]; q1.y = a4[3];
        g_feat4[(2*grp)*PPL + fidx] = q0;
        g_feat4[(2*grp+1)*PPL + fidx] = q1;
    } else {
        for (int idx = t; idx < 4096; idx += 256) {
            int c = idx >> 6, j = idx & 63;
            sw2[c*65 + j] = __ldg(&w2[idx]);
        }
        #pragma unroll
        for (int it = 0; it < 4; it++) {
            int item = t + it*256;
            int ph = item >> 6, c = item & 63;
            int py = ph >> 2, px = ph & 3;
            float ch = (py + 0.5f)/4.0f; ch = ch - floorf(ch + 0.001f) - 0.5f;
            float cw = (px + 0.5f)/4.0f; cw = cw - floorf(cw + 0.001f) - 0.5f;
            const float cs = 0.25f;
            float s = __ldg(&b1[c]);
            s = fmaf(__ldg(&w1[c*4+0]), cs, s);
            s = fmaf(__ldg(&w1[c*4+1]), cs, s);
            s = fmaf(__ldg(&w1[c*4+2]), ch, s);
            s = fmaf(__ldg(&w1[c*4+3]), cw, s);
            se1[item] = fmaxf(s, 0.0f);
        }
        __syncthreads();
        #pragma unroll
        for (int it = 0; it < 4; it++) {
            int item = t + it*256;
            int ph = item >> 6, c = item & 63;
            float s = __ldg(&b2[c]);
            #pragma unroll 8
            for (int j = 0; j < 64; j++)
                s = fmaf(sw2[c*65 + j], se1[ph*64 + j], s);
            se2[item] = fmaxf(s, 0.0f);
        }
        __syncthreads();
        if (t < 96) {
            int ph = t / 6, which = t % 6;
            if (which < 2) {
                float s = __ldg(&ob[which]);
                for (int j = 0; j < 64; j++)
                    s = fmaf(__ldg(&ow[which*64 + j]), se2[ph*64 + j], s);
                g_off[ph*2 + which] = s;
            } else {
                int e = which - 2;
                float s = __ldg(&rb[e]);
                for (int j = 0; j < 64; j++)
                    s = fmaf(__ldg(&rw[e*64 + j]), se2[ph*64 + j], s);
                g_r[ph*4 + e] = 1.0f/(1.0f + expf(-s));
            }
        }
    }
}

// border element enumerator for a 132x132 plane with 2-wide zero ring (1040 items)
__device__ __forceinline__ int border_index(int e) {
    int row, col;
    if (e < 528) {
        int r = e / 132;
        row = (r < 2) ? r : r + 128;
        col = e % 132;
    } else {
        int e2 = e - 528;
        row = 2 + (e2 & 127);
        int c = e2 >> 7;
        col = (c < 2) ? c : c + 128;
    }
    return row*132 + col;
}

// ============ Kernel 2: prep — B / mid pads / T / G interior / feat+G borders ============
__global__ void __launch_bounds__(512)
prep_kernel(const float* __restrict__ wc, const float* __restrict__ we,
            const float* __restrict__ tw) {
    __shared__ ull w2g[864];
    int b = blockIdx.x, tid = threadIdx.x;

    if (b < 16) {
        int u = b*512 + tid;                 // 8192 B entries
        int ph = u >> 9, rem = u & 511;
        int k = rem >> 6, c = rem & 63;
        float s = 0.0f;
        #pragma unroll
        for (int e = 0; e < 4; e++)
            s = fmaf(g_r[ph*4+e], __ldg(&wc[(e*8 + k)*64 + c]), s);
        g_B[ph*512 + k*64 + c] = s;
    } else if (b < 20) {
        int it = (b-16)*512 + tid;           // 2048 mid pad items
        if (it < 2048) {
            int j = it >> 10, r = (it >> 9) & 1, i = it & 511;
            ulonglong2 z; z.x = 0ULL; z.y = 0ULL;
            g_mid4[j*NPIX2 + (r ? 513*512 : 0) + i] = z;
        }
    } else if (b < 24) {
        int u = (b-20)*512 + tid;            // 1728 T entries
        if (u < 1728) {
            int k2 = u & 3, ph = (u >> 2) & 15, t9 = (u >> 6) % 9, o = u / 576;
            float s0 = 0.0f, s1 = 0.0f;
            #pragma unroll
            for (int e = 0; e < 4; e++) {
                float re = g_r[ph*4 + e];
                float a0 = 0.0f, a1 = 0.0f;
                for (int c = 0; c < 64; c++) {
                    float twv = __ldg(&tw[(o*64 + c)*9 + t9]);
                    a0 = fmaf(twv, __ldg(&we[(e*64 + c)*8 + 2*k2]),   a0);
                    a1 = fmaf(twv, __ldg(&we[(e*64 + c)*8 + 2*k2+1]), a1);
                }
                s0 = fmaf(re, a0, s0);
                s1 = fmaf(re, a1, s1);
            }
            g_T2[((o*9 + t9)*16 + ph)*4 + k2] = pk2(s0, s1);
        }
    } else if (b < 56) {
        // G interior
        for (int idx = tid; idx < 864; idx += 512) {
            int c2 = idx / 27, r = idx % 27, t9 = r / 3, o = r % 3;
            w2g[idx] = pk2(__ldg(&tw[(o*64 + 2*c2)*9 + t9]),
                           __ldg(&tw[(o*64 + 2*c2 + 1)*9 + t9]));
        }
        __syncthreads();
        int pix = (b - 24)*512 + tid;
        int x = pix & 127, y = pix >> 7;
        int fidx = (y+2)*132 + (x+2);
        ull a[27];
        #pragma unroll
        for (int j = 0; j < 27; j++) a[j] = 0ULL;
        for (int c4 = 0; c4 < 16; c4++) {
            ulonglong2 f = g_feat4[c4*PPL + fidx];
            #pragma unroll
            for (int j = 0; j < 27; j++) {
                a[j] = fma2(f.x, w2g[(2*c4)*27 + j], a[j]);
                a[j] = fma2(f.y, w2g[(2*c4+1)*27 + j], a[j]);
            }
        }
        #pragma unroll
        for (int t9 = 0; t9 < 9; t9++) {
            float l, h;
            float4 v;
            upk2(a[t9*3+0], l, h); v.x = l + h;
            upk2(a[t9*3+1], l, h); v.y = l + h;
            upk2(a[t9*3+2], l, h); v.z = l + h;
            v.w = 0.0f;
            g_G4[t9*PPL + fidx] = v;
        }
    } else if (b < 89) {
        int it = (b-56)*512 + tid;           // 16640 feat border items
        if (it < 16640) {
            int plane = it / 1040, e = it % 1040;
            ulonglong2 z; z.x = 0ULL; z.y = 0ULL;
            g_feat4[plane*PPL + border_index(e)] = z;
        }
    } else {
        int it = (b-89)*512 + tid;           // 9360 G border items
        if (it < 9360) {
            int plane = it / 1040, e = it % 1040;
            g_G4[plane*PPL + border_index(e)] = make_float4(0.f, 0.f, 0.f, 0.f);
        }
    }
}

// ============ Kernel 3: fused grid-sample + mid = B*fea0 (padded feat, packed mid out) ============
__global__ void __launch_bounds__(128)
main_fused() {
    __shared__ ull sBt[4*264];   // [phl][c2*8+k] = (B[k][2c2], B[k][2c2+1])

    int tid = threadIdx.x;
    int p0 = blockIdx.x << 7;
    int y  = p0 >> 9;
    int X0 = p0 & 511;
    int py4 = y & 3;

    const ull* GB = (const ull*)g_B;
    for (int i = tid; i < 1024; i += 128) {
        int phl = i >> 8, ii = i & 255;
        int c2 = ii >> 3, k = ii & 7;
        int ph = py4*4 + phl;
        sBt[phl*264 + ii] = GB[ph*256 + k*32 + c2];
    }
    __syncthreads();

    int w    = tid >> 5;
    int lane = tid & 31;
    int x = X0 + 4*lane + w;
    int ph = py4*4 + w;

    float off0 = g_off[ph*2+0];
    float off1 = g_off[ph*2+1];

    float xs = fminf(fmaxf(((float)x + 0.5f)*0.25f - 0.5f + off0, -1.5f), 128.5f);
    float ys = fminf(fmaxf(((float)y + 0.5f)*0.25f - 0.5f + off1, -1.5f), 128.5f);
    int x0 = __float2int_rd(xs), y0 = __float2int_rd(ys);
    float wx1 = xs - (float)x0, wx0 = 1.0f - wx1;
    float wy1 = ys - (float)y0, wy0 = 1.0f - wy1;
    float w00 = wy0*wx0, w01 = wy0*wx1;
    float w10 = wy1*wx0, w11 = wy1*wx1;
    int base = (y0+2)*132 + (x0+2);

    ull W00 = pk2(w00,w00), W01 = pk2(w01,w01);
    ull W10 = pk2(w10,w10), W11 = pk2(w11,w11);

    ull acc[8] = {0,0,0,0,0,0,0,0};
    const ull* Bp = sBt + w*264;
    #pragma unroll
    for (int c4 = 0; c4 < 16; c4++) {
        const ulonglong2* fp = g_feat4 + c4*PPL;
        ulonglong2 q00 = __ldg(fp + base);
        ulonglong2 q01 = __ldg(fp + base + 1);
        ulonglong2 q10 = __ldg(fp + base + 132);
        ulonglong2 q11 = __ldg(fp + base + 133);
        ull flo = fma2(q11.x, W11, fma2(q10.x, W10, fma2(q01.x, W01, mul2(q00.x, W00))));
        ull fhi = fma2(q11.y, W11, fma2(q10.y, W10, fma2(q01.y, W01, mul2(q00.y, W00))));
        #pragma unroll
        for (int k = 0; k < 8; k++) {
            acc[k] = fma2(Bp[(2*c4)*8 + k],   flo, acc[k]);
            acc[k] = fma2(Bp[(2*c4+1)*8 + k], fhi, acc[k]);
        }
    }
    float m[8];
    #pragma unroll
    for (int k = 0; k < 8; k++) {
        float lo, hi; upk2(acc[k], lo, hi);
        m[k] = lo + hi;
    }

    int g = (X0 >> 2) + lane;
    int moff = ((y+1) << 9) + (w << 7) + g;
    ulonglong2 q0; q0.x = pk2(m[0], m[1]); q0.y = pk2(m[2], m[3]);
    ulonglong2 q1; q1.x = pk2(m[4], m[5]); q1.y = pk2(m[6], m[7]);
    g_mid4[moff] = q0;
    g_mid4[NPIX2 + moff] = q1;
}

// ============ Kernel 4: tail conv via padded G-planes + T*mid (packed loads) ============
__global__ void __launch_bounds__(128, 9)
tail_conv(const float* __restrict__ tb) {
    __shared__ ull sT[432];              // [(t9*4+pxp)*12 + o*4 + k2]
    __shared__ float s_off0[16], s_off1[16];

    int tid = threadIdx.x;
    int p0 = blockIdx.x << 7;
    int y  = p0 >> 9;
    int X0 = p0 & 511;
    int py4 = y & 3;

    for (int idx = tid; idx < 432; idx += 128) {
        int t9 = idx / 48, rem = idx % 48;
        int pxp = rem / 12, j = rem % 12;
        int o = j >> 2, k2 = j & 3;
        int dy = t9 / 3 - 1;
        int pyp = (py4 + dy + 4) & 3;
        int ph = pyp*4 + pxp;
        sT[idx] = g_T2[((o*9 + t9)*16 + ph)*4 + k2];
    }
    if (tid < 16) {
        s_off0[tid] = g_off[tid*2+0];
        s_off1[tid] = g_off[tid*2+1];
    }
    __syncthreads();

    int w    = tid >> 5;
    int lane = tid & 31;
    int x = X0 + 4*lane + w;
    int g = (X0 >> 2) + lane;

    float bx = ((float)x + 0.5f)*0.25f - 0.5f;
    float by = ((float)y + 0.5f)*0.25f - 0.5f;
    float txm = (x > 0)   ? 1.0f : 0.0f;
    float txp = (x < 511) ? 1.0f : 0.0f;
    float tym = (y > 0)   ? 1.0f : 0.0f;
    float typ = (y < 511) ? 1.0f : 0.0f;

    float po0 = 0.0f, po1 = 0.0f, po2 = 0.0f;
    ull a2[3] = {0ULL, 0ULL, 0ULL};

    #pragma unroll
    for (int t9 = 0; t9 < 9; t9++) {
        const int dy = t9/3 - 1;
        const int dx = t9%3 - 1;
        int wd  = w + dx;
        int pxp = wd & 3;
        int pyp = (py4 + dy + 4) & 3;
        int ph  = pyp*4 + pxp;

        // issue mid loads first (independent of weight math)
        int moff = ((y + 1 + dy) << 9) + (pxp << 7) + g + (wd >> 2);
        ulonglong2 q0 = __ldg(g_mid4 + moff);
        ulonglong2 q1 = __ldg(g_mid4 + NPIX2 + moff);

        float tm = (dx == 0 ? 1.0f : (dx < 0 ? txm : txp))
                 * (dy == 0 ? 1.0f : (dy < 0 ? tym : typ));

        float xs = fminf(fmaxf(bx + 0.25f*dx + s_off0[ph], -1.5f), 128.5f);
        float ys = fminf(fmaxf(by + 0.25f*dy + s_off1[ph], -1.5f), 128.5f);
        int x0 = __float2int_rd(xs), y0i = __float2int_rd(ys);
        int base = (y0i+2)*132 + (x0+2);

        const float4* Gp = g_G4 + t9*PPL;
        float4 v00 = __ldg(Gp + base);
        float4 v01 = __ldg(Gp + base + 1);
        float4 v10 = __ldg(Gp + base + 132);
        float4 v11 = __ldg(Gp + base + 133);

        float wx1 = xs - (float)x0, wx0 = 1.0f - wx1;
        float fy  = ys - (float)y0i;
        float wy1 = fy*tm, wy0 = (1.0f - fy)*tm;
        float w00 = wy0*wx0, w01 = wy0*wx1;
        float w10 = wy1*wx0, w11 = wy1*wx1;

        po0 = fmaf(w00,v00.x, fmaf(w01,v01.x, fmaf(w10,v10.x, fmaf(w11,v11.x, po0))));
        po1 = fmaf(w00,v00.y, fmaf(w01,v01.y, fmaf(w10,v10.y, fmaf(w11,v11.y, po1))));
        po2 = fmaf(w00,v00.z, fmaf(w01,v01.z, fmaf(w10,v10.z, fmaf(w11,v11.z, po2))));

        ull m0 = q0.x, m1 = q0.y, m2 = q1.x, m3 = q1.y;
        if (dx != 0 || dy != 0) {
            ull mm = pk2(tm, tm);
            m0 = mul2(m0, mm); m1 = mul2(m1, mm);
            m2 = mul2(m2, mm); m3 = mul2(m3, mm);
        }
        const ull* Tp = sT + (t9*4 + pxp)*12;
        a2[0] = fma2(Tp[0],m0, fma2(Tp[1],m1, fma2(Tp[2], m2, fma2(Tp[3], m3, a2[0]))));
        a2[1] = fma2(Tp[4],m0, fma2(Tp[5],m1, fma2(Tp[6], m2, fma2(Tp[7], m3, a2[1]))));
        a2[2] = fma2(Tp[8],m0, fma2(Tp[9],m1, fma2(Tp[10],m2, fma2(Tp[11],m3, a2[2]))));
    }

    float l, h;
    upk2(a2[0], l, h); po0 += l + h;
    upk2(a2[1], l, h); po1 += l + h;
    upk2(a2[2], l, h); po2 += l + h;
    g_pred4[(y << 9) + (w << 7) + g] =
        make_float4(po0 + __ldg(&tb[0]), po1 + __ldg(&tb[1]), po2 + __ldg(&tb[2]), 0.0f);
}

// ============ Kernel 5: query gather (nearest, round-half-even) ============
__global__ void gather_q(const float* __restrict__ coord,
                         const float* __restrict__ cell,
                         float* __restrict__ out) {
    int q = blockIdx.x*blockDim.x + threadIdx.x;
    if (q >= NQ) return;
    float cy = __ldg(&coord[q*2+0]);
    float cx = __ldg(&coord[q*2+1]);
    float ly = __ldg(&cell[q*2+0]);
    float lx = __ldg(&cell[q*2+1]);
    float gyq = fminf(fmaxf(cy - ly*0.5f + 1e-6f, -1.0f + 1e-6f), 1.0f - 1e-6f);
    float gxq = fminf(fmaxf(cx - lx*0.5f + 1e-6f, -1.0f + 1e-6f), 1.0f - 1e-6f);
    int xi = (int)rintf((gxq + 1.0f)*0.5f*511.0f);
    int yi = (int)rintf((gyq + 1.0f)*0.5f*511.0f);
    xi = min(max(xi,0),511);
    yi = min(max(yi,0),511);
    int idx = (yi << 9) + ((xi & 3) << 7) + (xi >> 2);
    float4 v = __ldg(&g_pred4[idx]);
    out[q*3+0] = v.x;
    out[q*3+1] = v.y;
    out[q*3+2] = v.z;
}

extern "C" void kernel_launch(void* const* d_in, const int* in_sizes, int n_in,
                              void* d_out, int out_size) {
    const float* inp    = (const float*)d_in[0];
    const float* coord  = (const float*)d_in[1];
    const float* cell   = (const float*)d_in[2];
    const float* enc_w  = (const float*)d_in[3];
    const float* enc_b  = (const float*)d_in[4];
    const float* body_w1= (const float*)d_in[5];
    const float* body_b1= (const float*)d_in[6];
    const float* body_w2= (const float*)d_in[7];
    const float* body_b2= (const float*)d_in[8];
    const float* rout_w = (const float*)d_in[9];
    const float* rout_b = (const float*)d_in[10];
    const float* off_w  = (const float*)d_in[11];
    const float* off_b  = (const float*)d_in[12];
    const float* tail_w = (const float*)d_in[13];
    const float* tail_b = (const float*)d_in[14];
    const float* wcmp   = (const float*)d_in[15];
    const float* wexp   = (const float*)d_in[16];
    float* out = (float*)d_out;

    k_enc_phase<<<513, 256>>>(inp, enc_w, enc_b,
                              body_w1, body_b1, body_w2, body_b2,
                              rout_w, rout_b, off_w, off_b);
    prep_kernel<<<108, 512>>>(wcmp, wexp, tail_w);
    main_fused<<<2048, 128>>>();
    tail_conv<<<2048, 128>>>(tail_b);
    gather_q<<<1024, 256>>>(coord, cell, out);
}

// round 14
// speedup vs baseline: 1.0446x; 1.0446x over previous
#include <cuda_runtime.h>
#include <cuda_bf16.h>

#define HLR 128
#define WLR 128
#define HH 512
#define WH 512
#define NPIX (HH*WH)      // 262144
#define NPIX2 (514*512)   // padded mid plane rows 0..513
#define NQ 262144
#define PPL 17424         // padded LR plane: 132*132, data at (y+2, x+2)

typedef unsigned long long ull;

// ---- packed f32x2 helpers (sm_103a: fma.rn.f32x2 -> FFMA2) ----
__device__ __forceinline__ ull pk2(float lo, float hi) {
    ull r; asm("mov.b64 %0, {%1, %2};" : "=l"(r) : "f"(lo), "f"(hi)); return r;
}
__device__ __forceinline__ void upk2(ull v, float& lo, float& hi) {
    asm("mov.b64 {%0, %1}, %2;" : "=f"(lo), "=f"(hi) : "l"(v));
}
__device__ __forceinline__ ull fma2(ull a, ull b, ull c) {
    ull d; asm("fma.rn.f32x2 %0, %1, %2, %3;" : "=l"(d) : "l"(a), "l"(b), "l"(c)); return d;
}
__device__ __forceinline__ ull mul2(ull a, ull b) {
    ull d; asm("mul.rn.f32x2 %0, %1, %2;" : "=l"(d) : "l"(a), "l"(b)); return d;
}

// ---- scratch (device globals: allocation-free) ----
__device__ __align__(16) ull g_feat2[32*HLR*WLR];      // 4 MB LR feat channel pairs [c2][pix] (unpadded)
__device__ __align__(16) ulonglong2 g_mid4[2*NPIX2];   // 8.4 MB mid, packed (k0k1,k2k3)/(k4k5,k6k7), permuted+pad rows
__device__ __align__(16) float4 g_G4[9*PPL];           // 2.5 MB PADDED G planes [tap][(y+2)*132+(x+2)]{o0,o1,o2,-}
__device__ __align__(16) ull g_T2[3*9*16*4];           // T k-pairs [o][tap][ph][k2]
__device__ __align__(16) float4 g_pred4[NPIX];         // 4 MB, phase-permuted
__device__ float g_off[16*2];
__device__ float g_r[16*4];
__device__ __align__(16) float g_B[16*512];            // [ph][k*64+c]

// ============ Kernel 1: encoder conv3x3 (blocks 0..511) + phase MLP (block 512) ============
__global__ void __launch_bounds__(256)
k_enc_phase(const float* __restrict__ inp,
            const float* __restrict__ ew, const float* __restrict__ eb,
            const float* __restrict__ w1, const float* __restrict__ b1,
            const float* __restrict__ w2, const float* __restrict__ b2,
            const float* __restrict__ rw, const float* __restrict__ rb,
            const float* __restrict__ ow, const float* __restrict__ ob) {
    __shared__ float sw[27*64];
    __shared__ float sb[64];
    __shared__ float sw2[64*65];
    __shared__ float se1[1024];
    __shared__ float se2[1024];
    int t = threadIdx.x;

    if (blockIdx.x < 512) {
        for (int idx = t; idx < 27*64; idx += 256) {
            int j = idx >> 6, c = idx & 63;
            sw[idx] = __ldg(&ew[c*27 + j]);
        }
        if (t < 64) sb[t] = __ldg(&eb[t]);
        __syncthreads();

        int px = blockIdx.x*32 + (t & 31);
        int grp = t >> 5;
        int x = px & 127, y = px >> 7;

        float in[27];
        #pragma unroll
        for (int ci = 0; ci < 3; ci++)
            #pragma unroll
            for (int ky = 0; ky < 3; ky++) {
                int yy = y + ky - 1;
                bool ry = ((unsigned)yy < 128u);
                #pragma unroll
                for (int kx = 0; kx < 3; kx++) {
                    int xx = x + kx - 1;
                    in[ci*9 + ky*3 + kx] = (ry && ((unsigned)xx < 128u))
                        ? __ldg(&inp[(ci*128 + yy)*128 + xx]) : 0.0f;
                }
            }
        #pragma unroll
        for (int u = 0; u < 2; u++) {
            int c4 = grp*2 + u;
            float4 acc = make_float4(sb[c4*4+0], sb[c4*4+1], sb[c4*4+2], sb[c4*4+3]);
            #pragma unroll
            for (int j = 0; j < 27; j++) {
                float fin = in[j];
                const float4 wv = *(const float4*)&sw[j*64 + c4*4];
                acc.x = fmaf(fin, wv.x, acc.x);
                acc.y = fmaf(fin, wv.y, acc.y);
                acc.z = fmaf(fin, wv.z, acc.z);
                acc.w = fmaf(fin, wv.w, acc.w);
            }
            g_feat2[(c4*2+0)*16384 + px] = pk2(acc.x, acc.y);
            g_feat2[(c4*2+1)*16384 + px] = pk2(acc.z, acc.w);
        }
    } else {
        for (int idx = t; idx < 4096; idx += 256) {
            int c = idx >> 6, j = idx & 63;
            sw2[c*65 + j] = __ldg(&w2[idx]);
        }
        #pragma unroll
        for (int it = 0; it < 4; it++) {
            int item = t + it*256;
            int ph = item >> 6, c = item & 63;
            int py = ph >> 2, px = ph & 3;
            float ch = (py + 0.5f)/4.0f; ch = ch - floorf(ch + 0.001f) - 0.5f;
            float cw = (px + 0.5f)/4.0f; cw = cw - floorf(cw + 0.001f) - 0.5f;
            const float cs = 0.25f;
            float s = __ldg(&b1[c]);
            s = fmaf(__ldg(&w1[c*4+0]), cs, s);
            s = fmaf(__ldg(&w1[c*4+1]), cs, s);
            s = fmaf(__ldg(&w1[c*4+2]), ch, s);
            s = fmaf(__ldg(&w1[c*4+3]), cw, s);
            se1[item] = fmaxf(s, 0.0f);
        }
        __syncthreads();
        #pragma unroll
        for (int it = 0; it < 4; it++) {
            int item = t + it*256;
            int ph = item >> 6, c = item & 63;
            float s = __ldg(&b2[c]);
            #pragma unroll 8
            for (int j = 0; j < 64; j++)
                s = fmaf(sw2[c*65 + j], se1[ph*64 + j], s);
            se2[item] = fmaxf(s, 0.0f);
        }
        __syncthreads();
        if (t < 96) {
            int ph = t / 6, which = t % 6;
            if (which < 2) {
                float s = __ldg(&ob[which]);
                for (int j = 0; j < 64; j++)
                    s = fmaf(__ldg(&ow[which*64 + j]), se2[ph*64 + j], s);
                g_off[ph*2 + which] = s;
            } else {
                int e = which - 2;
                float s = __ldg(&rb[e]);
                for (int j = 0; j < 64; j++)
                    s = fmaf(__ldg(&rw[e*64 + j]), se2[ph*64 + j], s);
                g_r[ph*4 + e] = 1.0f/(1.0f + expf(-s));
            }
        }
    }
}

// border element enumerator for a 132x132 plane with 2-wide zero ring (1040 items)
__device__ __forceinline__ int border_index(int e) {
    int row, col;
    if (e < 528) {
        int r = e / 132;
        row = (r < 2) ? r : r + 128;
        col = e % 132;
    } else {
        int e2 = e - 528;
        row = 2 + (e2 & 127);
        int c = e2 >> 7;
        col = (c < 2) ? c : c + 128;
    }
    return row*132 + col;
}

// ============ Kernel 2: prep — B / mid pads / T / G interior (padded) / G borders ============
__global__ void __launch_bounds__(512)
prep_kernel(const float* __restrict__ wc, const float* __restrict__ we,
            const float* __restrict__ tw) {
    __shared__ ull w2g[864];
    int b = blockIdx.x, tid = threadIdx.x;

    if (b < 16) {
        int u = b*512 + tid;                 // 8192 B entries
        int ph = u >> 9, rem = u & 511;
        int k = rem >> 6, c = rem & 63;
        float s = 0.0f;
        #pragma unroll
        for (int e = 0; e < 4; e++)
            s = fmaf(g_r[ph*4+e], __ldg(&wc[(e*8 + k)*64 + c]), s);
        g_B[ph*512 + k*64 + c] = s;
    } else if (b < 20) {
        int it = (b-16)*512 + tid;           // 2048 mid pad items
        if (it < 2048) {
            int j = it >> 10, r = (it >> 9) & 1, i = it & 511;
            ulonglong2 z; z.x = 0ULL; z.y = 0ULL;
            g_mid4[j*NPIX2 + (r ? 513*512 : 0) + i] = z;
        }
    } else if (b < 24) {
        int u = (b-20)*512 + tid;            // 1728 T entries
        if (u < 1728) {
            int k2 = u & 3, ph = (u >> 2) & 15, t9 = (u >> 6) % 9, o = u / 576;
            float s0 = 0.0f, s1 = 0.0f;
            #pragma unroll
            for (int e = 0; e < 4; e++) {
                float re = g_r[ph*4 + e];
                float a0 = 0.0f, a1 = 0.0f;
                for (int c = 0; c < 64; c++) {
                    float twv = __ldg(&tw[(o*64 + c)*9 + t9]);
                    a0 = fmaf(twv, __ldg(&we[(e*64 + c)*8 + 2*k2]),   a0);
                    a1 = fmaf(twv, __ldg(&we[(e*64 + c)*8 + 2*k2+1]), a1);
                }
                s0 = fmaf(re, a0, s0);
                s1 = fmaf(re, a1, s1);
            }
            g_T2[((o*9 + t9)*16 + ph)*4 + k2] = pk2(s0, s1);
        }
    } else if (b < 56) {
        // G interior: read unpadded feat2, write PADDED G planes
        for (int idx = tid; idx < 864; idx += 512) {
            int c2 = idx / 27, r = idx % 27, t9 = r / 3, o = r % 3;
            w2g[idx] = pk2(__ldg(&tw[(o*64 + 2*c2)*9 + t9]),
                           __ldg(&tw[(o*64 + 2*c2 + 1)*9 + t9]));
        }
        __syncthreads();
        int pix = (b - 24)*512 + tid;
        int x = pix & 127, y = pix >> 7;
        int gidx = (y+2)*132 + (x+2);
        ull a[27];
        #pragma unroll
        for (int j = 0; j < 27; j++) a[j] = 0ULL;
        for (int c2 = 0; c2 < 32; c2++) {
            ull f = g_feat2[c2*16384 + pix];
            #pragma unroll
            for (int j = 0; j < 27; j++)
                a[j] = fma2(f, w2g[c2*27 + j], a[j]);
        }
        #pragma unroll
        for (int t9 = 0; t9 < 9; t9++) {
            float l, h;
            float4 v;
            upk2(a[t9*3+0], l, h); v.x = l + h;
            upk2(a[t9*3+1], l, h); v.y = l + h;
            upk2(a[t9*3+2], l, h); v.z = l + h;
            v.w = 0.0f;
            g_G4[t9*PPL + gidx] = v;
        }
    } else {
        int it = (b-56)*512 + tid;           // 9360 G border items
        if (it < 9360) {
            int plane = it / 1040, e = it % 1040;
            g_G4[plane*PPL + border_index(e)] = make_float4(0.f, 0.f, 0.f, 0.f);
        }
    }
}

// ============ Kernel 3: fused grid-sample + mid = B*fea0 (R9-style masked, packed mid out) ============
__global__ void __launch_bounds__(128)
main_fused() {
    __shared__ ull sBt[4*264];   // [phl][c2*8+k] = (B[k][2c2], B[k][2c2+1])

    int tid = threadIdx.x;
    int p0 = blockIdx.x << 7;
    int y  = p0 >> 9;
    int X0 = p0 & 511;
    int py4 = y & 3;

    const ull* GB = (const ull*)g_B;
    for (int i = tid; i < 1024; i += 128) {
        int phl = i >> 8, ii = i & 255;
        int c2 = ii >> 3, k = ii & 7;
        int ph = py4*4 + phl;
        sBt[phl*264 + ii] = GB[ph*256 + k*32 + c2];
    }
    __syncthreads();

    int w    = tid >> 5;
    int lane = tid & 31;
    int x = X0 + 4*lane + w;
    int ph = py4*4 + w;

    float off0 = g_off[ph*2+0];
    float off1 = g_off[ph*2+1];

    float xs = ((float)x + 0.5f)*0.25f - 0.5f + off0;
    float ys = ((float)y + 0.5f)*0.25f - 0.5f + off1;
    float x0f = floorf(xs), y0f = floorf(ys);
    float wx1 = xs - x0f, wx0 = 1.0f - wx1;
    float wy1 = ys - y0f, wy0 = 1.0f - wy1;
    int x0 = (int)x0f, y0 = (int)y0f;
    int x1 = x0 + 1, y1 = y0 + 1;
    float mx0 = ((unsigned)x0 < 128u) ? 1.0f : 0.0f;
    float mx1 = ((unsigned)x1 < 128u) ? 1.0f : 0.0f;
    float my0 = ((unsigned)y0 < 128u) ? 1.0f : 0.0f;
    float my1 = ((unsigned)y1 < 128u) ? 1.0f : 0.0f;
    float w00 = wy0*wx0*my0*mx0;
    float w01 = wy0*wx1*my0*mx1;
    float w10 = wy1*wx0*my1*mx0;
    float w11 = wy1*wx1*my1*mx1;
    int xc0 = min(max(x0,0),127), xc1 = min(max(x1,0),127);
    int yc0 = min(max(y0,0),127), yc1 = min(max(y1,0),127);
    int i00 = yc0*128 + xc0, i01 = yc0*128 + xc1;
    int i10 = yc1*128 + xc0, i11 = yc1*128 + xc1;

    ull W00 = pk2(w00,w00), W01 = pk2(w01,w01);
    ull W10 = pk2(w10,w10), W11 = pk2(w11,w11);

    ull acc[8] = {0,0,0,0,0,0,0,0};
    const ull* Bp = sBt + w*264;
    #pragma unroll
    for (int c2 = 0; c2 < 32; c2++) {
        const ull* fp = g_feat2 + c2*16384;
        ull f = fma2(__ldg(fp+i11), W11,
                fma2(__ldg(fp+i10), W10,
                fma2(__ldg(fp+i01), W01,
                mul2(__ldg(fp+i00), W00))));
        #pragma unroll
        for (int k = 0; k < 8; k++)
            acc[k] = fma2(Bp[c2*8 + k], f, acc[k]);
    }
    float m[8];
    #pragma unroll
    for (int k = 0; k < 8; k++) {
        float lo, hi; upk2(acc[k], lo, hi);
        m[k] = lo + hi;
    }

    int g = (X0 >> 2) + lane;
    int moff = ((y+1) << 9) + (w << 7) + g;
    ulonglong2 q0; q0.x = pk2(m[0], m[1]); q0.y = pk2(m[2], m[3]);
    ulonglong2 q1; q1.x = pk2(m[4], m[5]); q1.y = pk2(m[6], m[7]);
    g_mid4[moff] = q0;
    g_mid4[NPIX2 + moff] = q1;
}

// ============ Kernel 4: tail conv — padded G, packed mid, 2-deep software pipeline ============
__global__ void __launch_bounds__(128, 4)
tail_conv(const float* __restrict__ tb) {
    __shared__ ull sT[432];              // [(t9*4+pxp)*12 + o*4 + k2]
    __shared__ float s_off0[16], s_off1[16];

    int tid = threadIdx.x;
    int p0 = blockIdx.x << 7;
    int y  = p0 >> 9;
    int X0 = p0 & 511;
    int py4 = y & 3;

    for (int idx = tid; idx < 432; idx += 128) {
        int t9 = idx / 48, rem = idx % 48;
        int pxp = rem / 12, j = rem % 12;
        int o = j >> 2, k2 = j & 3;
        int dy = t9 / 3 - 1;
        int pyp = (py4 + dy + 4) & 3;
        int ph = pyp*4 + pxp;
        sT[idx] = g_T2[((o*9 + t9)*16 + ph)*4 + k2];
    }
    if (tid < 16) {
        s_off0[tid] = g_off[tid*2+0];
        s_off1[tid] = g_off[tid*2+1];
    }
    __syncthreads();

    int w    = tid >> 5;
    int lane = tid & 31;
    int x = X0 + 4*lane + w;
    int g = (X0 >> 2) + lane;

    float bx = ((float)x + 0.5f)*0.25f - 0.5f;
    float by = ((float)y + 0.5f)*0.25f - 0.5f;
    float txm = (x > 0)   ? 1.0f : 0.0f;
    float txp = (x < 511) ? 1.0f : 0.0f;
    float tym = (y > 0)   ? 1.0f : 0.0f;
    float typ = (y < 511) ? 1.0f : 0.0f;

    float po0 = 0.0f, po1 = 0.0f, po2 = 0.0f;
    ull a2[3] = {0ULL, 0ULL, 0ULL};

    // double buffers (register-resident; indices compile-time in unrolled loop)
    float4 vb[2][4];
    ulonglong2 mb[2][2];
    float xsb[2], ysb[2], tmb[2];
    int x0b[2], y0b[2], pxpb[2];

    #pragma unroll
    for (int t = 0; t <= 9; t++) {
        if (t < 9) {
            const int dy = t/3 - 1;
            const int dx = t%3 - 1;
            const int bfi = t & 1;
            int wd  = w + dx;
            int pxp = wd & 3;
            int ph  = ((py4 + dy + 4) & 3)*4 + pxp;
            float xs = fminf(fmaxf(bx + 0.25f*dx + s_off0[ph], -1.5f), 128.5f);
            float ys = fminf(fmaxf(by + 0.25f*dy + s_off1[ph], -1.5f), 128.5f);
            int x0 = __float2int_rd(xs), y0i = __float2int_rd(ys);
            int base = t*PPL + (y0i+2)*132 + (x0+2);
            vb[bfi][0] = __ldg(g_G4 + base);
            vb[bfi][1] = __ldg(g_G4 + base + 1);
            vb[bfi][2] = __ldg(g_G4 + base + 132);
            vb[bfi][3] = __ldg(g_G4 + base + 133);
            int moff = ((y + 1 + dy) << 9) + (pxp << 7) + g + (wd >> 2);
            mb[bfi][0] = __ldg(g_mid4 + moff);
            mb[bfi][1] = __ldg(g_mid4 + NPIX2 + moff);
            xsb[bfi] = xs; ysb[bfi] = ys;
            x0b[bfi] = x0; y0b[bfi] = y0i; pxpb[bfi] = pxp;
            tmb[bfi] = (dy == 0 ? 1.0f : (dy < 0 ? tym : typ))
                     * (dx == 0 ? 1.0f : (dx < 0 ? txm : txp));
        }
        if (t > 0) {
            const int tc = t - 1;
            const int bfi = tc & 1;
            float wx1 = xsb[bfi] - (float)x0b[bfi], wx0 = 1.0f - wx1;
            float fy  = ysb[bfi] - (float)y0b[bfi];
            float tm  = tmb[bfi];
            float wy1 = fy*tm, wy0 = (1.0f - fy)*tm;
            float w00 = wy0*wx0, w01 = wy0*wx1;
            float w10 = wy1*wx0, w11 = wy1*wx1;
            po0 = fmaf(w00,vb[bfi][0].x, fmaf(w01,vb[bfi][1].x,
                  fmaf(w10,vb[bfi][2].x, fmaf(w11,vb[bfi][3].x, po0))));
            po1 = fmaf(w00,vb[bfi][0].y, fmaf(w01,vb[bfi][1].y,
                  fmaf(w10,vb[bfi][2].y, fmaf(w11,vb[bfi][3].y, po1))));
            po2 = fmaf(w00,vb[bfi][0].z, fmaf(w01,vb[bfi][1].z,
                  fmaf(w10,vb[bfi][2].z, fmaf(w11,vb[bfi][3].z, po2))));

            ull m0 = mb[bfi][0].x, m1 = mb[bfi][0].y;
            ull m2 = mb[bfi][1].x, m3 = mb[bfi][1].y;
            if (tc != 4) {                 // center tap: tm == 1
                ull mm = pk2(tm, tm);
                m0 = mul2(m0, mm); m1 = mul2(m1, mm);
                m2 = mul2(m2, mm); m3 = mul2(m3, mm);
            }
            const ull* Tp = sT + (tc*4 + pxpb[bfi])*12;
            a2[0] = fma2(Tp[0],m0, fma2(Tp[1],m1, fma2(Tp[2], m2, fma2(Tp[3], m3, a2[0]))));
            a2[1] = fma2(Tp[4],m0, fma2(Tp[5],m1, fma2(Tp[6], m2, fma2(Tp[7], m3, a2[1]))));
            a2[2] = fma2(Tp[8],m0, fma2(Tp[9],m1, fma2(Tp[10],m2, fma2(Tp[11],m3, a2[2]))));
        }
    }

    float l, h;
    upk2(a2[0], l, h); po0 += l + h;
    upk2(a2[1], l, h); po1 += l + h;
    upk2(a2[2], l, h); po2 += l + h;
    g_pred4[(y << 9) + (w << 7) + g] =
        make_float4(po0 + __ldg(&tb[0]), po1 + __ldg(&tb[1]), po2 + __ldg(&tb[2]), 0.0f);
}

// ============ Kernel 5: query gather (nearest, round-half-even) ============
__global__ void gather_q(const float* __restrict__ coord,
                         const float* __restrict__ cell,
                         float* __restrict__ out) {
    int q = blockIdx.x*blockDim.x + threadIdx.x;
    if (q >= NQ) return;
    float cy = __ldg(&coord[q*2+0]);
    float cx = __ldg(&coord[q*2+1]);
    float ly = __ldg(&cell[q*2+0]);
    float lx = __ldg(&cell[q*2+1]);
    float gyq = fminf(fmaxf(cy - ly*0.5f + 1e-6f, -1.0f + 1e-6f), 1.0f - 1e-6f);
    float gxq = fminf(fmaxf(cx - lx*0.5f + 1e-6f, -1.0f + 1e-6f), 1.0f - 1e-6f);
    int xi = (int)rintf((gxq + 1.0f)*0.5f*511.0f);
    int yi = (int)rintf((gyq + 1.0f)*0.5f*511.0f);
    xi = min(max(xi,0),511);
    yi = min(max(yi,0),511);
    int idx = (yi << 9) + ((xi & 3) << 7) + (xi >> 2);
    float4 v = __ldg(&g_pred4[idx]);
    out[q*3+0] = v.x;
    out[q*3+1] = v.y;
    out[q*3+2] = v.z;
}

extern "C" void kernel_launch(void* const* d_in, const int* in_sizes, int n_in,
                              void* d_out, int out_size) {
    const float* inp    = (const float*)d_in[0];
    const float* coord  = (const float*)d_in[1];
    const float* cell   = (const float*)d_in[2];
    const float* enc_w  = (const float*)d_in[3];
    const float* enc_b  = (const float*)d_in[4];
    const float* body_w1= (const float*)d_in[5];
    const float* body_b1= (const float*)d_in[6];
    const float* body_w2= (const float*)d_in[7];
    const float* body_b2= (const float*)d_in[8];
    const float* rout_w = (const float*)d_in[9];
    const float* rout_b = (const float*)d_in[10];
    const float* off_w  = (const float*)d_in[11];
    const float* off_b  = (const float*)d_in[12];
    const float* tail_w = (const float*)d_in[13];
    const float* tail_b = (const float*)d_in[14];
    const float* wcmp   = (const float*)d_in[15];
    const float* wexp   = (const float*)d_in[16];
    float* out = (float*)d_out;

    k_enc_phase<<<513, 256>>>(inp, enc_w, enc_b,
                              body_w1, body_b1, body_w2, body_b2,
                              rout_w, rout_b, off_w, off_b);
    prep_kernel<<<75, 512>>>(wcmp, wexp, tail_w);
    main_fused<<<2048, 128>>>();
    tail_conv<<<2048, 128>>>(tail_b);
    gather_q<<<1024, 256>>>(coord, cell, out);
}

// round 15
// speedup vs baseline: 1.0598x; 1.0146x over previous
#include <cuda_runtime.h>
#include <cuda_bf16.h>

#define HLR 128
#define WLR 128
#define HH 512
#define WH 512
#define NPIX (HH*WH)      // 262144
#define NPIX2 (514*512)   // padded mid plane rows 0..513
#define NQ 262144
#define PPL 17424         // padded LR plane: 132*132, data at (y+2, x+2)

typedef unsigned long long ull;

// ---- packed f32x2 helpers (sm_103a: fma.rn.f32x2 -> FFMA2) ----
__device__ __forceinline__ ull pk2(float lo, float hi) {
    ull r; asm("mov.b64 %0, {%1, %2};" : "=l"(r) : "f"(lo), "f"(hi)); return r;
}
__device__ __forceinline__ void upk2(ull v, float& lo, float& hi) {
    asm("mov.b64 {%0, %1}, %2;" : "=f"(lo), "=f"(hi) : "l"(v));
}
__device__ __forceinline__ ull fma2(ull a, ull b, ull c) {
    ull d; asm("fma.rn.f32x2 %0, %1, %2, %3;" : "=l"(d) : "l"(a), "l"(b), "l"(c)); return d;
}
__device__ __forceinline__ ull mul2(ull a, ull b) {
    ull d; asm("mul.rn.f32x2 %0, %1, %2;" : "=l"(d) : "l"(a), "l"(b)); return d;
}

// ---- scratch (device globals: allocation-free) ----
__device__ __align__(16) ull g_feat2[32*HLR*WLR];      // 4 MB LR feat channel pairs [c2][pix] (unpadded)
__device__ __align__(16) ulonglong2 g_mid4[2*NPIX2];   // 8.4 MB mid, packed (k0k1,k2k3)/(k4k5,k6k7), permuted+pad rows
__device__ __align__(16) float4 g_G4[9*PPL];           // 2.5 MB PADDED G planes [tap][(y+2)*132+(x+2)]{o0,o1,o2,-}
__device__ __align__(16) ull g_T2[3*9*16*4];           // T k-pairs [o][tap][ph][k2]
__device__ __align__(16) float4 g_pred4[NPIX];         // 4 MB, phase-permuted
__device__ float g_off[16*2];
__device__ float g_r[16*4];
__device__ __align__(16) float g_B[16*512];            // [ph][k*64+c]

// ============ Kernel 1: encoder conv3x3 (blocks 0..511) + phase MLP (block 512) ============
__global__ void __launch_bounds__(256)
k_enc_phase(const float* __restrict__ inp,
            const float* __restrict__ ew, const float* __restrict__ eb,
            const float* __restrict__ w1, const float* __restrict__ b1,
            const float* __restrict__ w2, const float* __restrict__ b2,
            const float* __restrict__ rw, const float* __restrict__ rb,
            const float* __restrict__ ow, const float* __restrict__ ob) {
    __shared__ float sw[27*64];
    __shared__ float sb[64];
    __shared__ float sw2[64*65];
    __shared__ float se1[1024];
    __shared__ float se2[1024];
    int t = threadIdx.x;

    if (blockIdx.x < 512) {
        for (int idx = t; idx < 27*64; idx += 256) {
            int j = idx >> 6, c = idx & 63;
            sw[idx] = __ldg(&ew[c*27 + j]);
        }
        if (t < 64) sb[t] = __ldg(&eb[t]);
        __syncthreads();

        int px = blockIdx.x*32 + (t & 31);
        int grp = t >> 5;
        int x = px & 127, y = px >> 7;

        float in[27];
        #pragma unroll
        for (int ci = 0; ci < 3; ci++)
            #pragma unroll
            for (int ky = 0; ky < 3; ky++) {
                int yy = y + ky - 1;
                bool ry = ((unsigned)yy < 128u);
                #pragma unroll
                for (int kx = 0; kx < 3; kx++) {
                    int xx = x + kx - 1;
                    in[ci*9 + ky*3 + kx] = (ry && ((unsigned)xx < 128u))
                        ? __ldg(&inp[(ci*128 + yy)*128 + xx]) : 0.0f;
                }
            }
        #pragma unroll
        for (int u = 0; u < 2; u++) {
            int c4 = grp*2 + u;
            float4 acc = make_float4(sb[c4*4+0], sb[c4*4+1], sb[c4*4+2], sb[c4*4+3]);
            #pragma unroll
            for (int j = 0; j < 27; j++) {
                float fin = in[j];
                const float4 wv = *(const float4*)&sw[j*64 + c4*4];
                acc.x = fmaf(fin, wv.x, acc.x);
                acc.y = fmaf(fin, wv.y, acc.y);
                acc.z = fmaf(fin, wv.z, acc.z);
                acc.w = fmaf(fin, wv.w, acc.w);
            }
            g_feat2[(c4*2+0)*16384 + px] = pk2(acc.x, acc.y);
            g_feat2[(c4*2+1)*16384 + px] = pk2(acc.z, acc.w);
        }
    } else {
        for (int idx = t; idx < 4096; idx += 256) {
            int c = idx >> 6, j = idx & 63;
            sw2[c*65 + j] = __ldg(&w2[idx]);
        }
        #pragma unroll
        for (int it = 0; it < 4; it++) {
            int item = t + it*256;
            int ph = item >> 6, c = item & 63;
            int py = ph >> 2, px = ph & 3;
            float ch = (py + 0.5f)/4.0f; ch = ch - floorf(ch + 0.001f) - 0.5f;
            float cw = (px + 0.5f)/4.0f; cw = cw - floorf(cw + 0.001f) - 0.5f;
            const float cs = 0.25f;
            float s = __ldg(&b1[c]);
            s = fmaf(__ldg(&w1[c*4+0]), cs, s);
            s = fmaf(__ldg(&w1[c*4+1]), cs, s);
            s = fmaf(__ldg(&w1[c*4+2]), ch, s);
            s = fmaf(__ldg(&w1[c*4+3]), cw, s);
            se1[item] = fmaxf(s, 0.0f);
        }
        __syncthreads();
        #pragma unroll
        for (int it = 0; it < 4; it++) {
            int item = t + it*256;
            int ph = item >> 6, c = item & 63;
            float s = __ldg(&b2[c]);
            #pragma unroll 8
            for (int j = 0; j < 64; j++)
                s = fmaf(sw2[c*65 + j], se1[ph*64 + j], s);
            se2[item] = fmaxf(s, 0.0f);
        }
        __syncthreads();
        if (t < 96) {
            int ph = t / 6, which = t % 6;
            if (which < 2) {
                float s = __ldg(&ob[which]);
                for (int j = 0; j < 64; j++)
                    s = fmaf(__ldg(&ow[which*64 + j]), se2[ph*64 + j], s);
                g_off[ph*2 + which] = s;
            } else {
                int e = which - 2;
                float s = __ldg(&rb[e]);
                for (int j = 0; j < 64; j++)
                    s = fmaf(__ldg(&rw[e*64 + j]), se2[ph*64 + j], s);
                g_r[ph*4 + e] = 1.0f/(1.0f + expf(-s));
            }
        }
    }
}

// border element enumerator for a 132x132 plane with 2-wide zero ring (1040 items)
__device__ __forceinline__ int border_index(int e) {
    int row, col;
    if (e < 528) {
        int r = e / 132;
        row = (r < 2) ? r : r + 128;
        col = e % 132;
    } else {
        int e2 = e - 528;
        row = 2 + (e2 & 127);
        int c = e2 >> 7;
        col = (c < 2) ? c : c + 128;
    }
    return row*132 + col;
}

// ============ Kernel 2: prep — B / mid pads / T / G interior (padded) / G borders ============
__global__ void __launch_bounds__(512)
prep_kernel(const float* __restrict__ wc, const float* __restrict__ we,
            const float* __restrict__ tw) {
    __shared__ ull w2g[864];
    int b = blockIdx.x, tid = threadIdx.x;

    if (b < 16) {
        int u = b*512 + tid;                 // 8192 B entries
        int ph = u >> 9, rem = u & 511;
        int k = rem >> 6, c = rem & 63;
        float s = 0.0f;
        #pragma unroll
        for (int e = 0; e < 4; e++)
            s = fmaf(g_r[ph*4+e], __ldg(&wc[(e*8 + k)*64 + c]), s);
        g_B[ph*512 + k*64 + c] = s;
    } else if (b < 20) {
        int it = (b-16)*512 + tid;           // 2048 mid pad items
        if (it < 2048) {
            int j = it >> 10, r = (it >> 9) & 1, i = it & 511;
            ulonglong2 z; z.x = 0ULL; z.y = 0ULL;
            g_mid4[j*NPIX2 + (r ? 513*512 : 0) + i] = z;
        }
    } else if (b < 24) {
        int u = (b-20)*512 + tid;            // 1728 T entries
        if (u < 1728) {
            int k2 = u & 3, ph = (u >> 2) & 15, t9 = (u >> 6) % 9, o = u / 576;
            float s0 = 0.0f, s1 = 0.0f;
            #pragma unroll
            for (int e = 0; e < 4; e++) {
                float re = g_r[ph*4 + e];
                float a0 = 0.0f, a1 = 0.0f;
                for (int c = 0; c < 64; c++) {
                    float twv = __ldg(&tw[(o*64 + c)*9 + t9]);
                    a0 = fmaf(twv, __ldg(&we[(e*64 + c)*8 + 2*k2]),   a0);
                    a1 = fmaf(twv, __ldg(&we[(e*64 + c)*8 + 2*k2+1]), a1);
                }
                s0 = fmaf(re, a0, s0);
                s1 = fmaf(re, a1, s1);
            }
            g_T2[((o*9 + t9)*16 + ph)*4 + k2] = pk2(s0, s1);
        }
    } else if (b < 56) {
        // G interior: read unpadded feat2, write PADDED G planes
        for (int idx = tid; idx < 864; idx += 512) {
            int c2 = idx / 27, r = idx % 27, t9 = r / 3, o = r % 3;
            w2g[idx] = pk2(__ldg(&tw[(o*64 + 2*c2)*9 + t9]),
                           __ldg(&tw[(o*64 + 2*c2 + 1)*9 + t9]));
        }
        __syncthreads();
        int pix = (b - 24)*512 + tid;
        int x = pix & 127, y = pix >> 7;
        int gidx = (y+2)*132 + (x+2);
        ull a[27];
        #pragma unroll
        for (int j = 0; j < 27; j++) a[j] = 0ULL;
        for (int c2 = 0; c2 < 32; c2++) {
            ull f = g_feat2[c2*16384 + pix];
            #pragma unroll
            for (int j = 0; j < 27; j++)
                a[j] = fma2(f, w2g[c2*27 + j], a[j]);
        }
        #pragma unroll
        for (int t9 = 0; t9 < 9; t9++) {
            float l, h;
            float4 v;
            upk2(a[t9*3+0], l, h); v.x = l + h;
            upk2(a[t9*3+1], l, h); v.y = l + h;
            upk2(a[t9*3+2], l, h); v.z = l + h;
            v.w = 0.0f;
            g_G4[t9*PPL + gidx] = v;
        }
    } else {
        int it = (b-56)*512 + tid;           // 9360 G border items
        if (it < 9360) {
            int plane = it / 1040, e = it % 1040;
            g_G4[plane*PPL + border_index(e)] = make_float4(0.f, 0.f, 0.f, 0.f);
        }
    }
}

// ============ Kernel 3: fused grid-sample + mid = B*fea0 (R9-style masked, packed mid out) ============
__global__ void __launch_bounds__(128)
main_fused() {
    __shared__ ull sBt[4*264];   // [phl][c2*8+k] = (B[k][2c2], B[k][2c2+1])

    int tid = threadIdx.x;
    int p0 = blockIdx.x << 7;
    int y  = p0 >> 9;
    int X0 = p0 & 511;
    int py4 = y & 3;

    const ull* GB = (const ull*)g_B;
    for (int i = tid; i < 1024; i += 128) {
        int phl = i >> 8, ii = i & 255;
        int c2 = ii >> 3, k = ii & 7;
        int ph = py4*4 + phl;
        sBt[phl*264 + ii] = GB[ph*256 + k*32 + c2];
    }
    __syncthreads();

    int w    = tid >> 5;
    int lane = tid & 31;
    int x = X0 + 4*lane + w;
    int ph = py4*4 + w;

    float off0 = g_off[ph*2+0];
    float off1 = g_off[ph*2+1];

    float xs = ((float)x + 0.5f)*0.25f - 0.5f + off0;
    float ys = ((float)y + 0.5f)*0.25f - 0.5f + off1;
    float x0f = floorf(xs), y0f = floorf(ys);
    float wx1 = xs - x0f, wx0 = 1.0f - wx1;
    float wy1 = ys - y0f, wy0 = 1.0f - wy1;
    int x0 = (int)x0f, y0 = (int)y0f;
    int x1 = x0 + 1, y1 = y0 + 1;
    float mx0 = ((unsigned)x0 < 128u) ? 1.0f : 0.0f;
    float mx1 = ((unsigned)x1 < 128u) ? 1.0f : 0.0f;
    float my0 = ((unsigned)y0 < 128u) ? 1.0f : 0.0f;
    float my1 = ((unsigned)y1 < 128u) ? 1.0f : 0.0f;
    float w00 = wy0*wx0*my0*mx0;
    float w01 = wy0*wx1*my0*mx1;
    float w10 = wy1*wx0*my1*mx0;
    float w11 = wy1*wx1*my1*mx1;
    int xc0 = min(max(x0,0),127), xc1 = min(max(x1,0),127);
    int yc0 = min(max(y0,0),127), yc1 = min(max(y1,0),127);
    int i00 = yc0*128 + xc0, i01 = yc0*128 + xc1;
    int i10 = yc1*128 + xc0, i11 = yc1*128 + xc1;

    ull W00 = pk2(w00,w00), W01 = pk2(w01,w01);
    ull W10 = pk2(w10,w10), W11 = pk2(w11,w11);

    ull acc[8] = {0,0,0,0,0,0,0,0};
    const ull* Bp = sBt + w*264;
    #pragma unroll
    for (int c2 = 0; c2 < 32; c2++) {
        const ull* fp = g_feat2 + c2*16384;
        ull f = fma2(__ldg(fp+i11), W11,
                fma2(__ldg(fp+i10), W10,
                fma2(__ldg(fp+i01), W01,
                mul2(__ldg(fp+i00), W00))));
        #pragma unroll
        for (int k = 0; k < 8; k++)
            acc[k] = fma2(Bp[c2*8 + k], f, acc[k]);
    }
    float m[8];
    #pragma unroll
    for (int k = 0; k < 8; k++) {
        float lo, hi; upk2(acc[k], lo, hi);
        m[k] = lo + hi;
    }

    int g = (X0 >> 2) + lane;
    int moff = ((y+1) << 9) + (w << 7) + g;
    ulonglong2 q0; q0.x = pk2(m[0], m[1]); q0.y = pk2(m[2], m[3]);
    ulonglong2 q1; q1.x = pk2(m[4], m[5]); q1.y = pk2(m[6], m[7]);
    g_mid4[moff] = q0;
    g_mid4[NPIX2 + moff] = q1;
}

// ============ Kernel 4: tail conv — padded G, packed mid, 2-deep software pipeline ============
__global__ void __launch_bounds__(128, 4)
tail_conv(const float* __restrict__ tb) {
    __shared__ ull sT[432];              // [(t9*4+pxp)*12 + o*4 + k2]
    __shared__ float s_off0[16], s_off1[16];

    int tid = threadIdx.x;
    int p0 = blockIdx.x << 7;
    int y  = p0 >> 9;
    int X0 = p0 & 511;
    int py4 = y & 3;

    for (int idx = tid; idx < 432; idx += 128) {
        int t9 = idx / 48, rem = idx % 48;
        int pxp = rem / 12, j = rem % 12;
        int o = j >> 2, k2 = j & 3;
        int dy = t9 / 3 - 1;
        int pyp = (py4 + dy + 4) & 3;
        int ph = pyp*4 + pxp;
        sT[idx] = g_T2[((o*9 + t9)*16 + ph)*4 + k2];
    }
    if (tid < 16) {
        s_off0[tid] = g_off[tid*2+0];
        s_off1[tid] = g_off[tid*2+1];
    }
    __syncthreads();

    int w    = tid >> 5;
    int lane = tid & 31;
    int x = X0 + 4*lane + w;
    int g = (X0 >> 2) + lane;

    float bx = ((float)x + 0.5f)*0.25f - 0.5f;
    float by = ((float)y + 0.5f)*0.25f - 0.5f;
    float txm = (x > 0)   ? 1.0f : 0.0f;
    float txp = (x < 511) ? 1.0f : 0.0f;
    float tym = (y > 0)   ? 1.0f : 0.0f;
    float typ = (y < 511) ? 1.0f : 0.0f;

    float po0 = 0.0f, po1 = 0.0f, po2 = 0.0f;
    ull a2[3] = {0ULL, 0ULL, 0ULL};

    // double buffers (register-resident; indices compile-time in unrolled loop)
    float4 vb[2][4];
    ulonglong2 mb[2][2];
    float xsb[2], ysb[2], tmb[2];
    int x0b[2], y0b[2], pxpb[2];

    #pragma unroll
    for (int t = 0; t <= 9; t++) {
        if (t < 9) {
            const int dy = t/3 - 1;
            const int dx = t%3 - 1;
            const int bfi = t & 1;
            int wd  = w + dx;
            int pxp = wd & 3;
            int ph  = ((py4 + dy + 4) & 3)*4 + pxp;
            float xs = fminf(fmaxf(bx + 0.25f*dx + s_off0[ph], -1.5f), 128.5f);
            float ys = fminf(fmaxf(by + 0.25f*dy + s_off1[ph], -1.5f), 128.5f);
            int x0 = __float2int_rd(xs), y0i = __float2int_rd(ys);
            int base = t*PPL + (y0i+2)*132 + (x0+2);
            vb[bfi][0] = __ldg(g_G4 + base);
            vb[bfi][1] = __ldg(g_G4 + base + 1);
            vb[bfi][2] = __ldg(g_G4 + base + 132);
            vb[bfi][3] = __ldg(g_G4 + base + 133);
            int moff = ((y + 1 + dy) << 9) + (pxp << 7) + g + (wd >> 2);
            mb[bfi][0] = __ldg(g_mid4 + moff);
            mb[bfi][1] = __ldg(g_mid4 + NPIX2 + moff);
            xsb[bfi] = xs; ysb[bfi] = ys;
            x0b[bfi] = x0; y0b[bfi] = y0i; pxpb[bfi] = pxp;
            tmb[bfi] = (dy == 0 ? 1.0f : (dy < 0 ? tym : typ))
                     * (dx == 0 ? 1.0f : (dx < 0 ? txm : txp));
        }
        if (t > 0) {
            const int tc = t - 1;
            const int bfi = tc & 1;
            float wx1 = xsb[bfi] - (float)x0b[bfi], wx0 = 1.0f - wx1;
            float fy  = ysb[bfi] - (float)y0b[bfi];
            float tm  = tmb[bfi];
            float wy1 = fy*tm, wy0 = (1.0f - fy)*tm;
            float w00 = wy0*wx0, w01 = wy0*wx1;
            float w10 = wy1*wx0, w11 = wy1*wx1;
            po0 = fmaf(w00,vb[bfi][0].x, fmaf(w01,vb[bfi][1].x,
                  fmaf(w10,vb[bfi][2].x, fmaf(w11,vb[bfi][3].x, po0))));
            po1 = fmaf(w00,vb[bfi][0].y, fmaf(w01,vb[bfi][1].y,
                  fmaf(w10,vb[bfi][2].y, fmaf(w11,vb[bfi][3].y, po1))));
            po2 = fmaf(w00,vb[bfi][0].z, fmaf(w01,vb[bfi][1].z,
                  fmaf(w10,vb[bfi][2].z, fmaf(w11,vb[bfi][3].z, po2))));

            ull m0 = mb[bfi][0].x, m1 = mb[bfi][0].y;
            ull m2 = mb[bfi][1].x, m3 = mb[bfi][1].y;
            if (tc != 4) {                 // center tap: tm == 1
                ull mm = pk2(tm, tm);
                m0 = mul2(m0, mm); m1 = mul2(m1, mm);
                m2 = mul2(m2, mm); m3 = mul2(m3, mm);
            }
            const ull* Tp = sT + (tc*4 + pxpb[bfi])*12;
            a2[0] = fma2(Tp[0],m0, fma2(Tp[1],m1, fma2(Tp[2], m2, fma2(Tp[3], m3, a2[0]))));
            a2[1] = fma2(Tp[4],m0, fma2(Tp[5],m1, fma2(Tp[6], m2, fma2(Tp[7], m3, a2[1]))));
            a2[2] = fma2(Tp[8],m0, fma2(Tp[9],m1, fma2(Tp[10],m2, fma2(Tp[11],m3, a2[2]))));
        }
    }

    float l, h;
    upk2(a2[0], l, h); po0 += l + h;
    upk2(a2[1], l, h); po1 += l + h;
    upk2(a2[2], l, h); po2 += l + h;
    g_pred4[(y << 9) + (w << 7) + g] =
        make_float4(po0 + __ldg(&tb[0]), po1 + __ldg(&tb[1]), po2 + __ldg(&tb[2]), 0.0f);
}

// ============ Kernel 5: query gather (nearest, round-half-even) ============
__global__ void gather_q(const float* __restrict__ coord,
                         const float* __restrict__ cell,
                         float* __restrict__ out) {
    int q = blockIdx.x*blockDim.x + threadIdx.x;
    if (q >= NQ) return;
    float cy = __ldg(&coord[q*2+0]);
    float cx = __ldg(&coord[q*2+1]);
    float ly = __ldg(&cell[q*2+0]);
    float lx = __ldg(&cell[q*2+1]);
    float gyq = fminf(fmaxf(cy - ly*0.5f + 1e-6f, -1.0f + 1e-6f), 1.0f - 1e-6f);
    float gxq = fminf(fmaxf(cx - lx*0.5f + 1e-6f, -1.0f + 1e-6f), 1.0f - 1e-6f);
    int xi = (int)rintf((gxq + 1.0f)*0.5f*511.0f);
    int yi = (int)rintf((gyq + 1.0f)*0.5f*511.0f);
    xi = min(max(xi,0),511);
    yi = min(max(yi,0),511);
    int idx = (yi << 9) + ((xi & 3) << 7) + (xi >> 2);
    float4 v = __ldg(&g_pred4[idx]);
    out[q*3+0] = v.x;
    out[q*3+1] = v.y;
    out[q*3+2] = v.z;
}

extern "C" void kernel_launch(void* const* d_in, const int* in_sizes, int n_in,
                              void* d_out, int out_size) {
    const float* inp    = (const float*)d_in[0];
    const float* coord  = (const float*)d_in[1];
    const float* cell   = (const float*)d_in[2];
    const float* enc_w  = (const float*)d_in[3];
    const float* enc_b  = (const float*)d_in[4];
    const float* body_w1= (const float*)d_in[5];
    const float* body_b1= (const float*)d_in[6];
    const float* body_w2= (const float*)d_in[7];
    const float* body_b2= (const float*)d_in[8];
    const float* rout_w = (const float*)d_in[9];
    const float* rout_b = (const float*)d_in[10];
    const float* off_w  = (const float*)d_in[11];
    const float* off_b  = (const float*)d_in[12];
    const float* tail_w = (const float*)d_in[13];
    const float* tail_b = (const float*)d_in[14];
    const float* wcmp   = (const float*)d_in[15];
    const float* wexp   = (const float*)d_in[16];
    float* out = (float*)d_out;

    k_enc_phase<<<513, 256>>>(inp, enc_w, enc_b,
                              body_w1, body_b1, body_w2, body_b2,
                              rout_w, rout_b, off_w, off_b);
    prep_kernel<<<75, 512>>>(wcmp, wexp, tail_w);
    main_fused<<<2048, 128>>>();
    tail_conv<<<2048, 128>>>(tail_b);
    gather_q<<<1024, 256>>>(coord, cell, out);
}

// round 16
// speedup vs baseline: 1.0756x; 1.0148x over previous
#include <cuda_runtime.h>
#include <cuda_bf16.h>

#define HLR 128
#define WLR 128
#define HH 512
#define WH 512
#define NPIX (HH*WH)      // 262144
#define NPIX2 (514*512)   // padded mid plane rows 0..513
#define NQ 262144
#define PPL 17424         // padded LR plane: 132*132, data at (y+2, x+2)

typedef unsigned long long ull;

// ---- packed f32x2 helpers (sm_103a: fma.rn.f32x2 -> FFMA2) ----
__device__ __forceinline__ ull pk2(float lo, float hi) {
    ull r; asm("mov.b64 %0, {%1, %2};" : "=l"(r) : "f"(lo), "f"(hi)); return r;
}
__device__ __forceinline__ void upk2(ull v, float& lo, float& hi) {
    asm("mov.b64 {%0, %1}, %2;" : "=f"(lo), "=f"(hi) : "l"(v));
}
__device__ __forceinline__ ull fma2(ull a, ull b, ull c) {
    ull d; asm("fma.rn.f32x2 %0, %1, %2, %3;" : "=l"(d) : "l"(a), "l"(b), "l"(c)); return d;
}
__device__ __forceinline__ ull mul2(ull a, ull b) {
    ull d; asm("mul.rn.f32x2 %0, %1, %2;" : "=l"(d) : "l"(a), "l"(b)); return d;
}

// ---- scratch (device globals: allocation-free) ----
__device__ __align__(16) ull g_feat2[32*HLR*WLR];      // 4 MB LR feat channel pairs [c2][pix] (unpadded)
__device__ __align__(16) ulonglong2 g_mid4[2*NPIX2];   // 8.4 MB mid, packed (k0k1,k2k3)/(k4k5,k6k7), permuted+pad rows
__device__ __align__(16) float4 g_G4[9*PPL];           // 2.5 MB PADDED G planes [tap][(y+2)*132+(x+2)]{o0,o1,o2,-}
__device__ __align__(16) ull g_T2[3*9*16*4];           // T k-pairs [o][tap][ph][k2]
__device__ __align__(16) float4 g_pred4[NPIX];         // 4 MB, phase-permuted
__device__ float g_off[16*2];
__device__ float g_r[16*4];
__device__ __align__(16) float g_B[16*512];            // [ph][k*64+c]

// ============ Kernel 1: encoder conv3x3 (blocks 0..511) + phase MLP (block 512) ============
__global__ void __launch_bounds__(256)
k_enc_phase(const float* __restrict__ inp,
            const float* __restrict__ ew, const float* __restrict__ eb,
            const float* __restrict__ w1, const float* __restrict__ b1,
            const float* __restrict__ w2, const float* __restrict__ b2,
            const float* __restrict__ rw, const float* __restrict__ rb,
            const float* __restrict__ ow, const float* __restrict__ ob) {
    __shared__ float sw[27*64];
    __shared__ float sb[64];
    __shared__ float sw2[64*65];
    __shared__ float se1[1024];
    __shared__ float se2[1024];
    int t = threadIdx.x;

    if (blockIdx.x < 512) {
        for (int idx = t; idx < 27*64; idx += 256) {
            int j = idx >> 6, c = idx & 63;
            sw[idx] = __ldg(&ew[c*27 + j]);
        }
        if (t < 64) sb[t] = __ldg(&eb[t]);
        __syncthreads();

        int px = blockIdx.x*32 + (t & 31);
        int grp = t >> 5;
        int x = px & 127, y = px >> 7;

        float in[27];
        #pragma unroll
        for (int ci = 0; ci < 3; ci++)
            #pragma unroll
            for (int ky = 0; ky < 3; ky++) {
                int yy = y + ky - 1;
                bool ry = ((unsigned)yy < 128u);
                #pragma unroll
                for (int kx = 0; kx < 3; kx++) {
                    int xx = x + kx - 1;
                    in[ci*9 + ky*3 + kx] = (ry && ((unsigned)xx < 128u))
                        ? __ldg(&inp[(ci*128 + yy)*128 + xx]) : 0.0f;
                }
            }
        #pragma unroll
        for (int u = 0; u < 2; u++) {
            int c4 = grp*2 + u;
            float4 acc = make_float4(sb[c4*4+0], sb[c4*4+1], sb[c4*4+2], sb[c4*4+3]);
            #pragma unroll
            for (int j = 0; j < 27; j++) {
                float fin = in[j];
                const float4 wv = *(const float4*)&sw[j*64 + c4*4];
                acc.x = fmaf(fin, wv.x, acc.x);
                acc.y = fmaf(fin, wv.y, acc.y);
                acc.z = fmaf(fin, wv.z, acc.z);
                acc.w = fmaf(fin, wv.w, acc.w);
            }
            g_feat2[(c4*2+0)*16384 + px] = pk2(acc.x, acc.y);
            g_feat2[(c4*2+1)*16384 + px] = pk2(acc.z, acc.w);
        }
    } else {
        for (int idx = t; idx < 4096; idx += 256) {
            int c = idx >> 6, j = idx & 63;
            sw2[c*65 + j] = __ldg(&w2[idx]);
        }
        #pragma unroll
        for (int it = 0; it < 4; it++) {
            int item = t + it*256;
            int ph = item >> 6, c = item & 63;
            int py = ph >> 2, px = ph & 3;
            float ch = (py + 0.5f)/4.0f; ch = ch - floorf(ch + 0.001f) - 0.5f;
            float cw = (px + 0.5f)/4.0f; cw = cw - floorf(cw + 0.001f) - 0.5f;
            const float cs = 0.25f;
            float s = __ldg(&b1[c]);
            s = fmaf(__ldg(&w1[c*4+0]), cs, s);
            s = fmaf(__ldg(&w1[c*4+1]), cs, s);
            s = fmaf(__ldg(&w1[c*4+2]), ch, s);
            s = fmaf(__ldg(&w1[c*4+3]), cw, s);
            se1[item] = fmaxf(s, 0.0f);
        }
        __syncthreads();
        #pragma unroll
        for (int it = 0; it < 4; it++) {
            int item = t + it*256;
            int ph = item >> 6, c = item & 63;
            float s = __ldg(&b2[c]);
            #pragma unroll 8
            for (int j = 0; j < 64; j++)
                s = fmaf(sw2[c*65 + j], se1[ph*64 + j], s);
            se2[item] = fmaxf(s, 0.0f);
        }
        __syncthreads();
        if (t < 96) {
            int ph = t / 6, which = t % 6;
            if (which < 2) {
                float s = __ldg(&ob[which]);
                for (int j = 0; j < 64; j++)
                    s = fmaf(__ldg(&ow[which*64 + j]), se2[ph*64 + j], s);
                g_off[ph*2 + which] = s;
            } else {
                int e = which - 2;
                float s = __ldg(&rb[e]);
                for (int j = 0; j < 64; j++)
                    s = fmaf(__ldg(&rw[e*64 + j]), se2[ph*64 + j], s);
                g_r[ph*4 + e] = 1.0f/(1.0f + expf(-s));
            }
        }
    }
}

// border element enumerator for a 132x132 plane with 2-wide zero ring (1040 items)
__device__ __forceinline__ int border_index(int e) {
    int row, col;
    if (e < 528) {
        int r = e / 132;
        row = (r < 2) ? r : r + 128;
        col = e % 132;
    } else {
        int e2 = e - 528;
        row = 2 + (e2 & 127);
        int c = e2 >> 7;
        col = (c < 2) ? c : c + 128;
    }
    return row*132 + col;
}

// ============ Kernel 2: prep — B / mid pads / T / G interior (padded) / G borders ============
__global__ void __launch_bounds__(512)
prep_kernel(const float* __restrict__ wc, const float* __restrict__ we,
            const float* __restrict__ tw) {
    __shared__ ull w2g[864];
    int b = blockIdx.x, tid = threadIdx.x;

    if (b < 16) {
        int u = b*512 + tid;                 // 8192 B entries
        int ph = u >> 9, rem = u & 511;
        int k = rem >> 6, c = rem & 63;
        float s = 0.0f;
        #pragma unroll
        for (int e = 0; e < 4; e++)
            s = fmaf(g_r[ph*4+e], __ldg(&wc[(e*8 + k)*64 + c]), s);
        g_B[ph*512 + k*64 + c] = s;
    } else if (b < 20) {
        int it = (b-16)*512 + tid;           // 2048 mid pad items
        if (it < 2048) {
            int j = it >> 10, r = (it >> 9) & 1, i = it & 511;
            ulonglong2 z; z.x = 0ULL; z.y = 0ULL;
            g_mid4[j*NPIX2 + (r ? 513*512 : 0) + i] = z;
        }
    } else if (b < 24) {
        int u = (b-20)*512 + tid;            // 1728 T entries
        if (u < 1728) {
            int k2 = u & 3, ph = (u >> 2) & 15, t9 = (u >> 6) % 9, o = u / 576;
            float s0 = 0.0f, s1 = 0.0f;
            #pragma unroll
            for (int e = 0; e < 4; e++) {
                float re = g_r[ph*4 + e];
                float a0 = 0.0f, a1 = 0.0f;
                for (int c = 0; c < 64; c++) {
                    float twv = __ldg(&tw[(o*64 + c)*9 + t9]);
                    a0 = fmaf(twv, __ldg(&we[(e*64 + c)*8 + 2*k2]),   a0);
                    a1 = fmaf(twv, __ldg(&we[(e*64 + c)*8 + 2*k2+1]), a1);
                }
                s0 = fmaf(re, a0, s0);
                s1 = fmaf(re, a1, s1);
            }
            g_T2[((o*9 + t9)*16 + ph)*4 + k2] = pk2(s0, s1);
        }
    } else if (b < 56) {
        // G interior: read unpadded feat2, write PADDED G planes
        for (int idx = tid; idx < 864; idx += 512) {
            int c2 = idx / 27, r = idx % 27, t9 = r / 3, o = r % 3;
            w2g[idx] = pk2(__ldg(&tw[(o*64 + 2*c2)*9 + t9]),
                           __ldg(&tw[(o*64 + 2*c2 + 1)*9 + t9]));
        }
        __syncthreads();
        int pix = (b - 24)*512 + tid;
        int x = pix & 127, y = pix >> 7;
        int gidx = (y+2)*132 + (x+2);
        ull a[27];
        #pragma unroll
        for (int j = 0; j < 27; j++) a[j] = 0ULL;
        for (int c2 = 0; c2 < 32; c2++) {
            ull f = g_feat2[c2*16384 + pix];
            #pragma unroll
            for (int j = 0; j < 27; j++)
                a[j] = fma2(f, w2g[c2*27 + j], a[j]);
        }
        #pragma unroll
        for (int t9 = 0; t9 < 9; t9++) {
            float l, h;
            float4 v;
            upk2(a[t9*3+0], l, h); v.x = l + h;
            upk2(a[t9*3+1], l, h); v.y = l + h;
            upk2(a[t9*3+2], l, h); v.z = l + h;
            v.w = 0.0f;
            g_G4[t9*PPL + gidx] = v;
        }
    } else {
        int it = (b-56)*512 + tid;           // 9360 G border items
        if (it < 9360) {
            int plane = it / 1040, e = it % 1040;
            g_G4[plane*PPL + border_index(e)] = make_float4(0.f, 0.f, 0.f, 0.f);
        }
    }
}

// ============ Kernel 3: fused grid-sample + mid = B*fea0 (masked, packed mid out) ============
__global__ void __launch_bounds__(128)
main_fused() {
    __shared__ ull sBt[4*264];   // [phl][c2*8+k] = (B[k][2c2], B[k][2c2+1])

    int tid = threadIdx.x;
    int p0 = blockIdx.x << 7;
    int y  = p0 >> 9;
    int X0 = p0 & 511;
    int py4 = y & 3;

    const ull* GB = (const ull*)g_B;
    for (int i = tid; i < 1024; i += 128) {
        int phl = i >> 8, ii = i & 255;
        int c2 = ii >> 3, k = ii & 7;
        int ph = py4*4 + phl;
        sBt[phl*264 + ii] = GB[ph*256 + k*32 + c2];
    }
    __syncthreads();

    int w    = tid >> 5;
    int lane = tid & 31;
    int x = X0 + 4*lane + w;
    int ph = py4*4 + w;

    float off0 = g_off[ph*2+0];
    float off1 = g_off[ph*2+1];

    float xs = ((float)x + 0.5f)*0.25f - 0.5f + off0;
    float ys = ((float)y + 0.5f)*0.25f - 0.5f + off1;
    float x0f = floorf(xs), y0f = floorf(ys);
    float wx1 = xs - x0f, wx0 = 1.0f - wx1;
    float wy1 = ys - y0f, wy0 = 1.0f - wy1;
    int x0 = (int)x0f, y0 = (int)y0f;
    int x1 = x0 + 1, y1 = y0 + 1;
    float mx0 = ((unsigned)x0 < 128u) ? 1.0f : 0.0f;
    float mx1 = ((unsigned)x1 < 128u) ? 1.0f : 0.0f;
    float my0 = ((unsigned)y0 < 128u) ? 1.0f : 0.0f;
    float my1 = ((unsigned)y1 < 128u) ? 1.0f : 0.0f;
    float w00 = wy0*wx0*my0*mx0;
    float w01 = wy0*wx1*my0*mx1;
    float w10 = wy1*wx0*my1*mx0;
    float w11 = wy1*wx1*my1*mx1;
    int xc0 = min(max(x0,0),127), xc1 = min(max(x1,0),127);
    int yc0 = min(max(y0,0),127), yc1 = min(max(y1,0),127);
    int i00 = yc0*128 + xc0, i01 = yc0*128 + xc1;
    int i10 = yc1*128 + xc0, i11 = yc1*128 + xc1;

    ull W00 = pk2(w00,w00), W01 = pk2(w01,w01);
    ull W10 = pk2(w10,w10), W11 = pk2(w11,w11);

    ull acc[8] = {0,0,0,0,0,0,0,0};
    const ull* Bp = sBt + w*264;
    #pragma unroll
    for (int c2 = 0; c2 < 32; c2++) {
        const ull* fp = g_feat2 + c2*16384;
        ull f = fma2(__ldg(fp+i11), W11,
                fma2(__ldg(fp+i10), W10,
                fma2(__ldg(fp+i01), W01,
                mul2(__ldg(fp+i00), W00))));
        #pragma unroll
        for (int k = 0; k < 8; k++)
            acc[k] = fma2(Bp[c2*8 + k], f, acc[k]);
    }
    float m[8];
    #pragma unroll
    for (int k = 0; k < 8; k++) {
        float lo, hi; upk2(acc[k], lo, hi);
        m[k] = lo + hi;
    }

    int g = (X0 >> 2) + lane;
    int moff = ((y+1) << 9) + (w << 7) + g;
    ulonglong2 q0; q0.x = pk2(m[0], m[1]); q0.y = pk2(m[2], m[3]);
    ulonglong2 q1; q1.x = pk2(m[4], m[5]); q1.y = pk2(m[6], m[7]);
    g_mid4[moff] = q0;
    g_mid4[NPIX2 + moff] = q1;
}

// ============ Kernel 4: tail conv — padded G, packed mid, simple unrolled loop ============
__global__ void __launch_bounds__(128)
tail_conv(const float* __restrict__ tb) {
    __shared__ ull sT[432];              // [(t9*4+pxp)*12 + o*4 + k2]
    __shared__ float s_off0[16], s_off1[16];

    int tid = threadIdx.x;
    int p0 = blockIdx.x << 7;
    int y  = p0 >> 9;
    int X0 = p0 & 511;
    int py4 = y & 3;

    for (int idx = tid; idx < 432; idx += 128) {
        int t9 = idx / 48, rem = idx % 48;
        int pxp = rem / 12, j = rem % 12;
        int o = j >> 2, k2 = j & 3;
        int dy = t9 / 3 - 1;
        int pyp = (py4 + dy + 4) & 3;
        int ph = pyp*4 + pxp;
        sT[idx] = g_T2[((o*9 + t9)*16 + ph)*4 + k2];
    }
    if (tid < 16) {
        s_off0[tid] = g_off[tid*2+0];
        s_off1[tid] = g_off[tid*2+1];
    }
    __syncthreads();

    int w    = tid >> 5;
    int lane = tid & 31;
    int x = X0 + 4*lane + w;
    int g = (X0 >> 2) + lane;

    float bx = ((float)x + 0.5f)*0.25f - 0.5f;
    float by = ((float)y + 0.5f)*0.25f - 0.5f;
    float txm = (x > 0)   ? 1.0f : 0.0f;
    float txp = (x < 511) ? 1.0f : 0.0f;
    float tym = (y > 0)   ? 1.0f : 0.0f;
    float typ = (y < 511) ? 1.0f : 0.0f;

    float po0 = 0.0f, po1 = 0.0f, po2 = 0.0f;
    ull a2[3] = {0ULL, 0ULL, 0ULL};

    #pragma unroll
    for (int t9 = 0; t9 < 9; t9++) {
        const int dy = t9/3 - 1;
        const int dx = t9%3 - 1;
        int wd  = w + dx;
        int pxp = wd & 3;
        int ph  = ((py4 + dy + 4) & 3)*4 + pxp;

        // mid loads issued first (independent)
        int moff = ((y + 1 + dy) << 9) + (pxp << 7) + g + (wd >> 2);
        ulonglong2 q0 = __ldg(g_mid4 + moff);
        ulonglong2 q1 = __ldg(g_mid4 + NPIX2 + moff);

        float xs = fminf(fmaxf(bx + 0.25f*dx + s_off0[ph], -1.5f), 128.5f);
        float ys = fminf(fmaxf(by + 0.25f*dy + s_off1[ph], -1.5f), 128.5f);
        int x0 = __float2int_rd(xs), y0i = __float2int_rd(ys);
        int base = t9*PPL + (y0i+2)*132 + (x0+2);

        float4 v00 = __ldg(g_G4 + base);
        float4 v01 = __ldg(g_G4 + base + 1);
        float4 v10 = __ldg(g_G4 + base + 132);
        float4 v11 = __ldg(g_G4 + base + 133);

        float tm = (dx == 0 ? 1.0f : (dx < 0 ? txm : txp))
                 * (dy == 0 ? 1.0f : (dy < 0 ? tym : typ));
        float wx1 = xs - (float)x0, wx0 = 1.0f - wx1;
        float fy  = ys - (float)y0i;
        float wy1 = fy*tm, wy0 = (1.0f - fy)*tm;
        float w00 = wy0*wx0, w01 = wy0*wx1;
        float w10 = wy1*wx0, w11 = wy1*wx1;

        po0 = fmaf(w00,v00.x, fmaf(w01,v01.x, fmaf(w10,v10.x, fmaf(w11,v11.x, po0))));
        po1 = fmaf(w00,v00.y, fmaf(w01,v01.y, fmaf(w10,v10.y, fmaf(w11,v11.y, po1))));
        po2 = fmaf(w00,v00.z, fmaf(w01,v01.z, fmaf(w10,v10.z, fmaf(w11,v11.z, po2))));

        ull m0 = q0.x, m1 = q0.y, m2 = q1.x, m3 = q1.y;
        if (dx != 0 || dy != 0) {
            ull mm = pk2(tm, tm);
            m0 = mul2(m0, mm); m1 = mul2(m1, mm);
            m2 = mul2(m2, mm); m3 = mul2(m3, mm);
        }
        const ull* Tp = sT + (t9*4 + pxp)*12;
        a2[0] = fma2(Tp[0],m0, fma2(Tp[1],m1, fma2(Tp[2], m2, fma2(Tp[3], m3, a2[0]))));
        a2[1] = fma2(Tp[4],m0, fma2(Tp[5],m1, fma2(Tp[6], m2, fma2(Tp[7], m3, a2[1]))));
        a2[2] = fma2(Tp[8],m0, fma2(Tp[9],m1, fma2(Tp[10],m2, fma2(Tp[11],m3, a2[2]))));
    }

    float l, h;
    upk2(a2[0], l, h); po0 += l + h;
    upk2(a2[1], l, h); po1 += l + h;
    upk2(a2[2], l, h); po2 += l + h;
    g_pred4[(y << 9) + (w << 7) + g] =
        make_float4(po0 + __ldg(&tb[0]), po1 + __ldg(&tb[1]), po2 + __ldg(&tb[2]), 0.0f);
}

// ============ Kernel 5: query gather (nearest, round-half-even) ============
__global__ void gather_q(const float* __restrict__ coord,
                         const float* __restrict__ cell,
                         float* __restrict__ out) {
    int q = blockIdx.x*blockDim.x + threadIdx.x;
    if (q >= NQ) return;
    float cy = __ldg(&coord[q*2+0]);
    float cx = __ldg(&coord[q*2+1]);
    float ly = __ldg(&cell[q*2+0]);
    float lx = __ldg(&cell[q*2+1]);
    float gyq = fminf(fmaxf(cy - ly*0.5f + 1e-6f, -1.0f + 1e-6f), 1.0f - 1e-6f);
    float gxq = fminf(fmaxf(cx - lx*0.5f + 1e-6f, -1.0f + 1e-6f), 1.0f - 1e-6f);
    int xi = (int)rintf((gxq + 1.0f)*0.5f*511.0f);
    int yi = (int)rintf((gyq + 1.0f)*0.5f*511.0f);
    xi = min(max(xi,0),511);
    yi = min(max(yi,0),511);
    int idx = (yi << 9) + ((xi & 3) << 7) + (xi >> 2);
    float4 v = __ldg(&g_pred4[idx]);
    out[q*3+0] = v.x;
    out[q*3+1] = v.y;
    out[q*3+2] = v.z;
}

extern "C" void kernel_launch(void* const* d_in, const int* in_sizes, int n_in,
                              void* d_out, int out_size) {
    const float* inp    = (const float*)d_in[0];
    const float* coord  = (const float*)d_in[1];
    const float* cell   = (const float*)d_in[2];
    const float* enc_w  = (const float*)d_in[3];
    const float* enc_b  = (const float*)d_in[4];
    const float* body_w1= (const float*)d_in[5];
    const float* body_b1= (const float*)d_in[6];
    const float* body_w2= (const float*)d_in[7];
    const float* body_b2= (const float*)d_in[8];
    const float* rout_w = (const float*)d_in[9];
    const float* rout_b = (const float*)d_in[10];
    const float* off_w  = (const float*)d_in[11];
    const float* off_b  = (const float*)d_in[12];
    const float* tail_w = (const float*)d_in[13];
    const float* tail_b = (const float*)d_in[14];
    const float* wcmp   = (const float*)d_in[15];
    const float* wexp   = (const float*)d_in[16];
    float* out = (float*)d_out;

    k_enc_phase<<<513, 256>>>(inp, enc_w, enc_b,
                              body_w1, body_b1, body_w2, body_b2,
                              rout_w, rout_b, off_w, off_b);
    prep_kernel<<<75, 512>>>(wcmp, wexp, tail_w);
    main_fused<<<2048, 128>>>();
    tail_conv<<<2048, 128>>>(tail_b);
    gather_q<<<1024, 256>>>(coord, cell, out);
}